// round 11
// baseline (speedup 1.0000x reference)
#include <cuda_runtime.h>
#include <cuda_bf16.h>
#include <cstdint>

#define B_    16
#define FIN_  256
#define NTOK_ 1024
#define NH_   8
#define FH_   64
#define CIN_  258
#define CPAD_ 288
#define COUT_ 512

typedef __nv_bfloat16 bf16;

// ---------------------------------------------------------------------------
__device__ bf16 g_t[B_ * NTOK_ * CPAD_];          // [b][n][c] padded to 288
__device__ bf16 g_w[3 * COUT_ * CPAD_];           // packed qkv weights
__device__ bf16 g_wo[FIN_ * COUT_];               // wo
__device__ bf16 g_q[B_ * NH_ * NTOK_ * FH_];      // [b][h][n][d]
__device__ bf16 g_k[B_ * NH_ * NTOK_ * FH_];      // [b][h][n][d]
__device__ bf16 g_v[B_ * NH_ * FH_ * NTOK_];      // [b][h][d][n]
__device__ bf16 g_o[B_ * NTOK_ * COUT_];          // [b][n][h*64+d]

// ---------------------------------------------------------------------------
__device__ __forceinline__ uint32_t smem_u32(const void* p) {
    uint32_t a;
    asm("{ .reg .u64 t; cvta.to.shared.u64 t, %1; cvt.u32.u64 %0, t; }" : "=r"(a) : "l"(p));
    return a;
}
__device__ __forceinline__ void cp16(uint32_t sdst, const void* gsrc) {
    asm volatile("cp.async.cg.shared.global [%0], [%1], 16;" :: "r"(sdst), "l"(gsrc));
}
#define CP_COMMIT() asm volatile("cp.async.commit_group;" ::: "memory")
#define CP_WAIT(n)  asm volatile("cp.async.wait_group %0;" :: "n"(n) : "memory")

__device__ __forceinline__ uint32_t pack2(float lo, float hi) {
    uint32_t r;
    asm("cvt.rn.bf16x2.f32 %0, %1, %2;" : "=r"(r) : "f"(hi), "f"(lo));
    return r;
}
__device__ __forceinline__ uint32_t ex2_bf16x2(uint32_t a) {
    uint32_t r;
    asm("ex2.approx.ftz.bf16x2 %0, %1;" : "=r"(r) : "r"(a));
    return r;
}
__device__ __forceinline__ void ldsm4(uint32_t r[4], uint32_t addr) {
    asm volatile("ldmatrix.sync.aligned.m8n8.x4.shared.b16 {%0,%1,%2,%3}, [%4];"
        : "=r"(r[0]), "=r"(r[1]), "=r"(r[2]), "=r"(r[3]) : "r"(addr));
}
__device__ __forceinline__ void mma16(float c[4], const uint32_t a[4], uint32_t b0, uint32_t b1) {
    asm volatile(
        "mma.sync.aligned.m16n8k16.row.col.f32.bf16.bf16.f32 "
        "{%0,%1,%2,%3}, {%4,%5,%6,%7}, {%8,%9}, {%0,%1,%2,%3};"
        : "+f"(c[0]), "+f"(c[1]), "+f"(c[2]), "+f"(c[3])
        : "r"(a[0]), "r"(a[1]), "r"(a[2]), "r"(a[3]), "r"(b0), "r"(b1));
}

// ---------------------------------------------------------------------------
// Kernel 0 (fused): prep t_T, pack qkv weights, pack wo.
__global__ __launch_bounds__(256) void prep_pack(
    const float* __restrict__ x,
    const float* __restrict__ wq, const float* __restrict__ wk, const float* __restrict__ wv,
    const float* __restrict__ wo)
{
    const int blk = blockIdx.x;
    if (blk < 512) {
        __shared__ float tile[32][33];
        const int nt = blk & 31, b = blk >> 5;
        const int tx = threadIdx.x & 31, ty = threadIdx.x >> 5;
        const int n0 = nt * 32;
        for (int c0 = 0; c0 < CPAD_; c0 += 32) {
            for (int ci = ty; ci < 32; ci += 8) {
                const int c = c0 + ci, n = n0 + tx;
                float v = 0.f;
                if (c < FIN_)           v = x[((size_t)b * FIN_ + c) * NTOK_ + n];
                else if (c == FIN_)     v = -1.f + (2.f / 31.f) * (float)(n >> 5);
                else if (c == FIN_ + 1) v = -1.f + (2.f / 31.f) * (float)(n & 31);
                tile[ci][tx] = v;
            }
            __syncthreads();
            for (int ni = ty; ni < 32; ni += 8)
                g_t[((size_t)b * NTOK_ + n0 + ni) * CPAD_ + c0 + tx] =
                    __float2bfloat16_rn(tile[tx][ni]);
            __syncthreads();
        }
    } else if (blk < 512 + 1728) {
        const int i = (blk - 512) * 256 + threadIdx.x;
        const int r = i / CPAD_, c = i - r * CPAD_;
        const int sel = r >> 9, o = r & 511;
        const float* w = (sel == 0) ? wq : ((sel == 1) ? wk : wv);
        g_w[i] = __float2bfloat16_rn((c < CIN_) ? w[o * CIN_ + c] : 0.f);
    } else {
        const int i = (blk - 512 - 1728) * 256 + threadIdx.x;
        g_wo[i] = __float2bfloat16_rn(wo[i]);
    }
}

// ---------------------------------------------------------------------------
// GEMM: CTA tile 128(M) x 64(N), 8 warps (4m x 2n), warp 32x32.
// K-chunks 32 (2 k16 steps), 4-stage cp.async pipeline, one barrier per chunk.
#define ATILE (128 * 80)    // 10240
#define BTILE (64 * 80)     // 5120
#define STAGE (ATILE + BTILE)
__global__ __launch_bounds__(256, 3) void qkv_gemm(
    const float* __restrict__ bq, const float* __restrict__ bk, const float* __restrict__ bv)
{
    extern __shared__ uint32_t sm[];
    const uint32_t sb = smem_u32(sm);

    const int tid = threadIdx.x;
    const int warp = tid >> 5, lane = tid & 31;
    const int g = lane >> 2, t4 = lane & 3;
    const int wm = warp & 3, wn = warp >> 2;
    const int nt = blockIdx.x, mt = blockIdx.y, b = blockIdx.z;
    const int sel = mt >> 2;
    const int o0 = (mt & 3) * 128;
    const int n0 = nt * 64;
    const bf16* wsrc = g_w + (size_t)(sel * COUT_ + o0) * CPAD_;
    const bf16* bsrc = g_t + ((size_t)b * NTOK_ + n0) * CPAD_;
    const float* bias = (sel == 0) ? bq : ((sel == 1) ? bk : bv);

    const uint32_t aoff = (uint32_t)((wm * 32 + (lane & 15)) * 80 + (lane >> 4) * 16);
    const uint32_t boff = (uint32_t)((wn * 32 + (lane >> 4) * 8 + (lane & 7)) * 80
                                     + ((lane >> 3) & 1) * 16);

    auto loadAB = [&](int kc, int st) {
        const uint32_t ab = sb + (uint32_t)(st * STAGE);
        const uint32_t bb = ab + ATILE;
        #pragma unroll
        for (int it = 0; it < 2; it++) {
            const int i = tid + it * 256;
            const int r = i >> 2, c4 = i & 3;
            cp16(ab + (uint32_t)(r * 80 + c4 * 16), wsrc + (size_t)r * CPAD_ + kc * 32 + c4 * 8);
        }
        {
            const int r = tid >> 2, c4 = tid & 3;
            cp16(bb + (uint32_t)(r * 80 + c4 * 16), bsrc + (size_t)r * CPAD_ + kc * 32 + c4 * 8);
        }
    };

    float c[2][4][4];
    #pragma unroll
    for (int mi = 0; mi < 2; mi++)
        #pragma unroll
        for (int nf = 0; nf < 4; nf++)
            #pragma unroll
            for (int q = 0; q < 4; q++) c[mi][nf][q] = 0.f;

    loadAB(0, 0); CP_COMMIT();
    loadAB(1, 1); CP_COMMIT();
    loadAB(2, 2); CP_COMMIT();

    const int NK = CPAD_ / 32;  // 9
    for (int kc = 0; kc < NK; kc++) {
        if (kc + 2 < NK)      CP_WAIT(2);
        else if (kc + 1 < NK) CP_WAIT(1);
        else                  CP_WAIT(0);
        __syncthreads();
        if (kc + 3 < NK) { loadAB(kc + 3, (kc + 3) & 3); CP_COMMIT(); }
        const uint32_t Ab = sb + (uint32_t)((kc & 3) * STAGE);
        const uint32_t Bb = Ab + ATILE;
        #pragma unroll
        for (int s = 0; s < 2; s++) {
            uint32_t a[2][4];
            ldsm4(a[0], Ab + aoff + s * 32);
            ldsm4(a[1], Ab + aoff + 16 * 80 + s * 32);
            #pragma unroll
            for (int nfp = 0; nfp < 2; nfp++) {
                uint32_t bb4[4];
                ldsm4(bb4, Bb + boff + nfp * 16 * 80 + s * 32);
                mma16(c[0][nfp * 2],     a[0], bb4[0], bb4[1]);
                mma16(c[1][nfp * 2],     a[1], bb4[0], bb4[1]);
                mma16(c[0][nfp * 2 + 1], a[0], bb4[2], bb4[3]);
                mma16(c[1][nfp * 2 + 1], a[1], bb4[2], bb4[3]);
            }
        }
    }
    __syncthreads();

    float* Cs = (float*)sm;   // staging reuse: 64*132*4 = 33792 (< 61440 pipeline)
    if (sel < 2) {
        #pragma unroll
        for (int mi = 0; mi < 2; mi++) {
            const int m0 = wm * 32 + mi * 16;
            const float bv0 = bias[o0 + m0 + g];
            const float bv1 = bias[o0 + m0 + g + 8];
            #pragma unroll
            for (int nf = 0; nf < 4; nf++) {
                const int nn = wn * 32 + nf * 8 + t4 * 2;
                Cs[(nn)     * 132 + m0 + g]     = c[mi][nf][0] + bv0;
                Cs[(nn + 1) * 132 + m0 + g]     = c[mi][nf][1] + bv0;
                Cs[(nn)     * 132 + m0 + g + 8] = c[mi][nf][2] + bv1;
                Cs[(nn + 1) * 132 + m0 + g + 8] = c[mi][nf][3] + bv1;
            }
        }
        __syncthreads();
        bf16* dstbase = (sel == 0) ? g_q : g_k;
        #pragma unroll
        for (int it = 0; it < 8; it++) {
            const int i = tid + it * 256;
            const int nl = i >> 5, m4 = i & 31;
            const float4 cv = *(const float4*)&Cs[nl * 132 + m4 * 4];
            const int o = o0 + m4 * 4;
            const int h = o >> 6, d = o & 63;
            uint2 pk = make_uint2(pack2(cv.x, cv.y), pack2(cv.z, cv.w));
            *(uint2*)&dstbase[(((size_t)b * NH_ + h) * NTOK_ + n0 + nl) * FH_ + d] = pk;
        }
    } else {
        #pragma unroll
        for (int mi = 0; mi < 2; mi++) {
            #pragma unroll
            for (int half = 0; half < 2; half++) {
                const int m = wm * 32 + mi * 16 + g + half * 8;
                const int o = o0 + m;
                const int h = o >> 6, d = o & 63;
                const float bval = bias[o];
                bf16* dst = g_v + (((size_t)b * NH_ + h) * FH_ + d) * NTOK_ + n0;
                #pragma unroll
                for (int nf = 0; nf < 4; nf++) {
                    const int nn = wn * 32 + nf * 8 + t4 * 2;
                    *(uint32_t*)&dst[nn] = pack2(c[mi][nf][half * 2] + bval,
                                                 c[mi][nf][half * 2 + 1] + bval);
                }
            }
        }
    }
}

// ---------------------------------------------------------------------------
// Kernel 2: attention. 32-key chunks (32 iters), register-resident P,
// bf16x2 ex2, 4-stage K/V pipeline, one barrier per chunk. 3 CTAs/SM.
#define KSTG 4608      // 32 keys x 144B
#define VSTG 5120      // 64 d x 80B
__global__ __launch_bounds__(256, 3) void attn_kernel() {
    extern __shared__ uint32_t sm[];
    const uint32_t sb = smem_u32(sm);
    const uint32_t KsB = sb, VsB = sb + 4 * KSTG;

    const int tid = threadIdx.x;
    const int warp = tid >> 5, lane = tid & 31;
    const int g = lane >> 2, t4 = lane & 3;
    const int m0 = warp * 16;
    const int qt = blockIdx.x, h = blockIdx.y, b = blockIdx.z;
    const size_t hb = (size_t)(b * NH_ + h);
    const bf16* qsrc = g_q + hb * NTOK_ * FH_ + (size_t)qt * 128 * FH_;
    const bf16* ksrc = g_k + hb * NTOK_ * FH_;
    const bf16* vsrc = g_v + hb * FH_ * NTOK_;

    const uint32_t kvoffK = (uint32_t)(((lane >> 4) * 8 + (lane & 7)) * 144
                                       + ((lane >> 3) & 1) * 16);
    const uint32_t kvoffV = (uint32_t)(((lane >> 4) * 8 + (lane & 7)) * 80
                                       + ((lane >> 3) & 1) * 16);

    uint32_t qf[4][4];
    {
        const uint32_t* q0 = (const uint32_t*)(qsrc + (size_t)(m0 + g) * FH_);
        const uint32_t* q1 = (const uint32_t*)(qsrc + (size_t)(m0 + g + 8) * FH_);
        #pragma unroll
        for (int s = 0; s < 4; s++) {
            qf[s][0] = q0[s * 8 + t4];
            qf[s][1] = q1[s * 8 + t4];
            qf[s][2] = q0[s * 8 + t4 + 4];
            qf[s][3] = q1[s * 8 + t4 + 4];
        }
    }

    auto loadKV = [&](int ck, int st) {
        const int c0 = ck * 32;
        {   // K: 32 key rows x 64 d (144B pitch) — 256 cp16
            const int r = tid >> 3, c8 = tid & 7;
            cp16(KsB + (uint32_t)(st * KSTG + r * 144 + c8 * 16),
                 ksrc + (size_t)(c0 + r) * FH_ + c8 * 8);
        }
        {   // V: 64 d rows x 32 j (80B pitch) — 256 cp16
            const int r = tid >> 2, c4 = tid & 3;
            cp16(VsB + (uint32_t)(st * VSTG + r * 80 + c4 * 16),
                 vsrc + (size_t)r * NTOK_ + c0 + c4 * 8);
        }
    };

    float oacc[8][4];
    #pragma unroll
    for (int nf = 0; nf < 8; nf++)
        #pragma unroll
        for (int q = 0; q < 4; q++) oacc[nf][q] = 0.f;
    float l0 = 0.f, l1 = 0.f;

    loadKV(0, 0); CP_COMMIT();
    loadKV(1, 1); CP_COMMIT();
    loadKV(2, 2); CP_COMMIT();

    const float SC = 0.125f * 1.4426950408889634f;   // 1/sqrt(64) * log2(e)

    for (int ck = 0; ck < 32; ck++) {
        if (ck + 2 < 32)      CP_WAIT(2);
        else if (ck + 1 < 32) CP_WAIT(1);
        else                  CP_WAIT(0);
        __syncthreads();
        if (ck + 3 < 32) { loadKV(ck + 3, (ck + 3) & 3); CP_COMMIT(); }
        const uint32_t Kb = KsB + (uint32_t)((ck & 3) * KSTG);
        const uint32_t Vb = VsB + (uint32_t)((ck & 3) * VSTG);

        // S = Q K^T : 16q x 32key, contraction d=64 (4 k16 steps)
        float sc[4][4];
        #pragma unroll
        for (int nf = 0; nf < 4; nf++)
            #pragma unroll
            for (int q = 0; q < 4; q++) sc[nf][q] = 0.f;
        #pragma unroll
        for (int s = 0; s < 4; s++) {
            #pragma unroll
            for (int nfp = 0; nfp < 2; nfp++) {
                uint32_t bb4[4];
                ldsm4(bb4, Kb + kvoffK + nfp * 16 * 144 + s * 32);
                mma16(sc[nfp * 2],     qf[s], bb4[0], bb4[1]);
                mma16(sc[nfp * 2 + 1], qf[s], bb4[2], bb4[3]);
            }
        }

        // P = exp2(S*SC) in bf16x2 pairs (A-fragment layout), register-resident
        uint32_t pb[4][2];
        float s0 = 0.f, s1 = 0.f;
        #pragma unroll
        for (int nf = 0; nf < 4; nf++) {
            pb[nf][0] = ex2_bf16x2(pack2(sc[nf][0] * SC, sc[nf][1] * SC));
            pb[nf][1] = ex2_bf16x2(pack2(sc[nf][2] * SC, sc[nf][3] * SC));
            const float2 f0 = __bfloat1622float2(*(__nv_bfloat162*)&pb[nf][0]);
            const float2 f1 = __bfloat1622float2(*(__nv_bfloat162*)&pb[nf][1]);
            s0 += f0.x + f0.y;
            s1 += f1.x + f1.y;
        }
        s0 += __shfl_xor_sync(0xffffffffu, s0, 1);
        s0 += __shfl_xor_sync(0xffffffffu, s0, 2);
        s1 += __shfl_xor_sync(0xffffffffu, s1, 1);
        s1 += __shfl_xor_sync(0xffffffffu, s1, 2);
        l0 += s0; l1 += s1;

        // O += P V^T : contraction j=32 (2 k16 steps), n-dim d=64 (4 nfp)
        #pragma unroll
        for (int s = 0; s < 2; s++) {
            const uint32_t pa[4] = { pb[2 * s][0], pb[2 * s][1],
                                     pb[2 * s + 1][0], pb[2 * s + 1][1] };
            #pragma unroll
            for (int nfp = 0; nfp < 4; nfp++) {
                uint32_t bb4[4];
                ldsm4(bb4, Vb + kvoffV + nfp * 16 * 80 + s * 32);
                mma16(oacc[nfp * 2],     pa, bb4[0], bb4[1]);
                mma16(oacc[nfp * 2 + 1], pa, bb4[2], bb4[3]);
            }
        }
    }

    const float inv0 = 1.f / l0, inv1 = 1.f / l1;
    bf16* d0 = g_o + ((size_t)b * NTOK_ + qt * 128 + m0 + g) * COUT_ + h * FH_;
    bf16* d1 = d0 + 8 * COUT_;
    #pragma unroll
    for (int nf = 0; nf < 8; nf++) {
        const int dd = nf * 8 + t4 * 2;
        *(uint32_t*)&d0[dd] = pack2(oacc[nf][0] * inv0, oacc[nf][1] * inv0);
        *(uint32_t*)&d1[dd] = pack2(oacc[nf][2] * inv1, oacc[nf][3] * inv1);
    }
}

// ---------------------------------------------------------------------------
// Kernel 3: output projection + bias + residual. CTA 128x64, 3 CTAs/SM.
__global__ __launch_bounds__(256, 3) void oproj_gemm(
    const float* __restrict__ x, const float* __restrict__ bo, float* __restrict__ out)
{
    extern __shared__ uint32_t sm[];
    const uint32_t sb = smem_u32(sm);

    const int tid = threadIdx.x;
    const int warp = tid >> 5, lane = tid & 31;
    const int g = lane >> 2, t4 = lane & 3;
    const int wm = warp & 3, wn = warp >> 2;
    const int nt = blockIdx.x, mt = blockIdx.y, b = blockIdx.z;
    const int o0 = mt * 128, n0 = nt * 64;
    const bf16* asrc = g_wo + (size_t)o0 * COUT_;
    const bf16* bsrc = g_o + ((size_t)b * NTOK_ + n0) * COUT_;

    const uint32_t aoff = (uint32_t)((wm * 32 + (lane & 15)) * 80 + (lane >> 4) * 16);
    const uint32_t boff = (uint32_t)((wn * 32 + (lane >> 4) * 8 + (lane & 7)) * 80
                                     + ((lane >> 3) & 1) * 16);

    auto loadAB = [&](int kc, int st) {
        const uint32_t ab = sb + (uint32_t)(st * STAGE);
        const uint32_t bb = ab + ATILE;
        #pragma unroll
        for (int it = 0; it < 2; it++) {
            const int i = tid + it * 256;
            const int r = i >> 2, c4 = i & 3;
            cp16(ab + (uint32_t)(r * 80 + c4 * 16), asrc + (size_t)r * COUT_ + kc * 32 + c4 * 8);
        }
        {
            const int r = tid >> 2, c4 = tid & 3;
            cp16(bb + (uint32_t)(r * 80 + c4 * 16), bsrc + (size_t)r * COUT_ + kc * 32 + c4 * 8);
        }
    };

    float c[2][4][4];
    #pragma unroll
    for (int mi = 0; mi < 2; mi++)
        #pragma unroll
        for (int nf = 0; nf < 4; nf++)
            #pragma unroll
            for (int q = 0; q < 4; q++) c[mi][nf][q] = 0.f;

    loadAB(0, 0); CP_COMMIT();
    loadAB(1, 1); CP_COMMIT();
    loadAB(2, 2); CP_COMMIT();

    const int NK = 16;
    for (int kc = 0; kc < NK; kc++) {
        if (kc + 2 < NK)      CP_WAIT(2);
        else if (kc + 1 < NK) CP_WAIT(1);
        else                  CP_WAIT(0);
        __syncthreads();
        if (kc + 3 < NK) { loadAB(kc + 3, (kc + 3) & 3); CP_COMMIT(); }
        const uint32_t Ab = sb + (uint32_t)((kc & 3) * STAGE);
        const uint32_t Bb = Ab + ATILE;
        #pragma unroll
        for (int s = 0; s < 2; s++) {
            uint32_t a[2][4];
            ldsm4(a[0], Ab + aoff + s * 32);
            ldsm4(a[1], Ab + aoff + 16 * 80 + s * 32);
            #pragma unroll
            for (int nfp = 0; nfp < 2; nfp++) {
                uint32_t bb4[4];
                ldsm4(bb4, Bb + boff + nfp * 16 * 80 + s * 32);
                mma16(c[0][nfp * 2],     a[0], bb4[0], bb4[1]);
                mma16(c[1][nfp * 2],     a[1], bb4[0], bb4[1]);
                mma16(c[0][nfp * 2 + 1], a[0], bb4[2], bb4[3]);
                mma16(c[1][nfp * 2 + 1], a[1], bb4[2], bb4[3]);
            }
        }
    }

    #pragma unroll
    for (int mi = 0; mi < 2; mi++) {
        #pragma unroll
        for (int half = 0; half < 2; half++) {
            const int m = o0 + wm * 32 + mi * 16 + g + half * 8;
            const float bval = bo[m];
            const float* xr = x + ((size_t)b * FIN_ + m) * NTOK_ + n0;
            float* outr = out + ((size_t)b * FIN_ + m) * NTOK_ + n0;
            #pragma unroll
            for (int nf = 0; nf < 4; nf++) {
                const int nn = wn * 32 + nf * 8 + t4 * 2;
                const float2 xv = *(const float2*)&xr[nn];
                *(float2*)&outr[nn] = make_float2(xv.x + bval + c[mi][nf][half * 2],
                                                  xv.y + bval + c[mi][nf][half * 2 + 1]);
            }
        }
    }
}

// ---------------------------------------------------------------------------
extern "C" void kernel_launch(void* const* d_in, const int* in_sizes, int n_in,
                              void* d_out, int out_size)
{
    const float* x  = (const float*)d_in[0];
    const float* wq = (const float*)d_in[1];
    const float* bq = (const float*)d_in[2];
    const float* wk = (const float*)d_in[3];
    const float* bk = (const float*)d_in[4];
    const float* wv = (const float*)d_in[5];
    const float* bv = (const float*)d_in[6];
    const float* wo = (const float*)d_in[7];
    const float* bo = (const float*)d_in[8];
    float* out = (float*)d_out;

    const int gemm_smem = 4 * STAGE;             // 61440
    const int attn_smem = 4 * (KSTG + VSTG);     // 38912
    cudaFuncSetAttribute(qkv_gemm,    cudaFuncAttributeMaxDynamicSharedMemorySize, gemm_smem);
    cudaFuncSetAttribute(oproj_gemm,  cudaFuncAttributeMaxDynamicSharedMemorySize, gemm_smem);
    cudaFuncSetAttribute(attn_kernel, cudaFuncAttributeMaxDynamicSharedMemorySize, attn_smem);

    prep_pack<<<512 + 1728 + 512, 256>>>(x, wq, wk, wv, wo);
    qkv_gemm<<<dim3(16, 12, 16), 256, gemm_smem>>>(bq, bk, bv);
    attn_kernel<<<dim3(8, NH_, B_), 256, attn_smem>>>();
    oproj_gemm<<<dim3(16, 2, 16), 256, gemm_smem>>>(x, bo, out);
}

// round 12
// speedup vs baseline: 1.0847x; 1.0847x over previous
#include <cuda_runtime.h>
#include <cuda_bf16.h>
#include <cstdint>

#define B_    16
#define FIN_  256
#define NTOK_ 1024
#define NH_   8
#define FH_   64
#define CIN_  258
#define CPAD_ 288
#define COUT_ 512

typedef __nv_bfloat16 bf16;

// ---------------------------------------------------------------------------
__device__ bf16 g_t[B_ * NTOK_ * CPAD_];          // [b][n][c] padded to 288
__device__ bf16 g_w[3 * COUT_ * CPAD_];           // packed qkv weights
__device__ bf16 g_wo[FIN_ * COUT_];               // wo
__device__ bf16 g_q[B_ * NH_ * NTOK_ * FH_];      // [b][h][n][d]
__device__ bf16 g_k[B_ * NH_ * NTOK_ * FH_];      // [b][h][n][d]
__device__ bf16 g_v[B_ * NH_ * FH_ * NTOK_];      // [b][h][d][n]
__device__ bf16 g_o[B_ * NTOK_ * COUT_];          // [b][n][h*64+d]

// ---------------------------------------------------------------------------
__device__ __forceinline__ uint32_t smem_u32(const void* p) {
    uint32_t a;
    asm("{ .reg .u64 t; cvta.to.shared.u64 t, %1; cvt.u32.u64 %0, t; }" : "=r"(a) : "l"(p));
    return a;
}
__device__ __forceinline__ void cp16(uint32_t sdst, const void* gsrc) {
    asm volatile("cp.async.cg.shared.global [%0], [%1], 16;" :: "r"(sdst), "l"(gsrc));
}
#define CP_COMMIT() asm volatile("cp.async.commit_group;" ::: "memory")
#define CP_WAIT(n)  asm volatile("cp.async.wait_group %0;" :: "n"(n) : "memory")

__device__ __forceinline__ uint32_t pack2(float lo, float hi) {
    uint32_t r;
    asm("cvt.rn.bf16x2.f32 %0, %1, %2;" : "=r"(r) : "f"(hi), "f"(lo));
    return r;
}
__device__ __forceinline__ uint32_t ex2_bf16x2(uint32_t a) {
    uint32_t r;
    asm("ex2.approx.ftz.bf16x2 %0, %1;" : "=r"(r) : "r"(a));
    return r;
}
__device__ __forceinline__ void ldsm4(uint32_t r[4], uint32_t addr) {
    asm volatile("ldmatrix.sync.aligned.m8n8.x4.shared.b16 {%0,%1,%2,%3}, [%4];"
        : "=r"(r[0]), "=r"(r[1]), "=r"(r[2]), "=r"(r[3]) : "r"(addr));
}
__device__ __forceinline__ void mma16(float c[4], const uint32_t a[4], uint32_t b0, uint32_t b1) {
    asm volatile(
        "mma.sync.aligned.m16n8k16.row.col.f32.bf16.bf16.f32 "
        "{%0,%1,%2,%3}, {%4,%5,%6,%7}, {%8,%9}, {%0,%1,%2,%3};"
        : "+f"(c[0]), "+f"(c[1]), "+f"(c[2]), "+f"(c[3])
        : "r"(a[0]), "r"(a[1]), "r"(a[2]), "r"(a[3]), "r"(b0), "r"(b1));
}

// ---------------------------------------------------------------------------
// Kernel 0 (fused): prep t_T, pack qkv weights, pack wo.
__global__ __launch_bounds__(256) void prep_pack(
    const float* __restrict__ x,
    const float* __restrict__ wq, const float* __restrict__ wk, const float* __restrict__ wv,
    const float* __restrict__ wo)
{
    const int blk = blockIdx.x;
    if (blk < 512) {
        __shared__ float tile[32][33];
        const int nt = blk & 31, b = blk >> 5;
        const int tx = threadIdx.x & 31, ty = threadIdx.x >> 5;
        const int n0 = nt * 32;
        for (int c0 = 0; c0 < CPAD_; c0 += 32) {
            for (int ci = ty; ci < 32; ci += 8) {
                const int c = c0 + ci, n = n0 + tx;
                float v = 0.f;
                if (c < FIN_)           v = x[((size_t)b * FIN_ + c) * NTOK_ + n];
                else if (c == FIN_)     v = -1.f + (2.f / 31.f) * (float)(n >> 5);
                else if (c == FIN_ + 1) v = -1.f + (2.f / 31.f) * (float)(n & 31);
                tile[ci][tx] = v;
            }
            __syncthreads();
            for (int ni = ty; ni < 32; ni += 8)
                g_t[((size_t)b * NTOK_ + n0 + ni) * CPAD_ + c0 + tx] =
                    __float2bfloat16_rn(tile[tx][ni]);
            __syncthreads();
        }
    } else if (blk < 512 + 1728) {
        const int i = (blk - 512) * 256 + threadIdx.x;
        const int r = i / CPAD_, c = i - r * CPAD_;
        const int sel = r >> 9, o = r & 511;
        const float* w = (sel == 0) ? wq : ((sel == 1) ? wk : wv);
        g_w[i] = __float2bfloat16_rn((c < CIN_) ? w[o * CIN_ + c] : 0.f);
    } else {
        const int i = (blk - 512 - 1728) * 256 + threadIdx.x;
        g_wo[i] = __float2bfloat16_rn(wo[i]);
    }
}

// ---------------------------------------------------------------------------
// GEMM: CTA 128x128, 8 warps (4m x 2n), K-chunks 32 (2 k16 steps),
// 3-stage cp.async pipeline, one __syncthreads per chunk, ldmatrix fragments.
#define TSZB (128 * 80)
__global__ __launch_bounds__(256, 2) void qkv_gemm(
    const float* __restrict__ bq, const float* __restrict__ bk, const float* __restrict__ bv)
{
    extern __shared__ uint32_t sm[];
    const uint32_t sb = smem_u32(sm);

    const int tid = threadIdx.x;
    const int warp = tid >> 5, lane = tid & 31;
    const int g = lane >> 2, t4 = lane & 3;
    const int wm = warp & 3, wn = warp >> 2;
    const int nt = blockIdx.x, mt = blockIdx.y, b = blockIdx.z;
    const int sel = mt >> 2;
    const int o0 = (mt & 3) * 128;
    const int n0 = nt * 128;
    const bf16* wsrc = g_w + (size_t)(sel * COUT_ + o0) * CPAD_;
    const bf16* bsrc = g_t + ((size_t)b * NTOK_ + n0) * CPAD_;
    const float* bias = (sel == 0) ? bq : ((sel == 1) ? bk : bv);

    const uint32_t aoff = (uint32_t)((wm * 32 + (lane & 15)) * 80 + (lane >> 4) * 16);
    const uint32_t boff = (uint32_t)((wn * 64 + (lane >> 4) * 8 + (lane & 7)) * 80
                                     + ((lane >> 3) & 1) * 16);

    auto loadAB = [&](int kc, int st) {
        const uint32_t ab = sb + (uint32_t)(st * 2 * TSZB);
        const uint32_t bb = ab + TSZB;
        #pragma unroll
        for (int it = 0; it < 2; it++) {
            const int i = tid + it * 256;
            const int r = i >> 2, c4 = i & 3;
            cp16(ab + (uint32_t)(r * 80 + c4 * 16), wsrc + (size_t)r * CPAD_ + kc * 32 + c4 * 8);
            cp16(bb + (uint32_t)(r * 80 + c4 * 16), bsrc + (size_t)r * CPAD_ + kc * 32 + c4 * 8);
        }
    };

    float c[2][8][4];
    #pragma unroll
    for (int mi = 0; mi < 2; mi++)
        #pragma unroll
        for (int nf = 0; nf < 8; nf++)
            #pragma unroll
            for (int q = 0; q < 4; q++) c[mi][nf][q] = 0.f;

    loadAB(0, 0); CP_COMMIT();
    loadAB(1, 1); CP_COMMIT();

    const int NK = CPAD_ / 32;  // 9
    for (int kc = 0; kc < NK; kc++) {
        if (kc + 1 < NK) CP_WAIT(1); else CP_WAIT(0);
        __syncthreads();
        if (kc + 2 < NK) { loadAB(kc + 2, (kc + 2) % 3); CP_COMMIT(); }
        const uint32_t Ab = sb + (uint32_t)((kc % 3) * 2 * TSZB);
        const uint32_t Bb = Ab + TSZB;
        #pragma unroll
        for (int s = 0; s < 2; s++) {
            uint32_t a[2][4];
            ldsm4(a[0], Ab + aoff + s * 32);
            ldsm4(a[1], Ab + aoff + 16 * 80 + s * 32);
            #pragma unroll
            for (int nfp = 0; nfp < 4; nfp++) {
                uint32_t bb4[4];
                ldsm4(bb4, Bb + boff + nfp * 16 * 80 + s * 32);
                mma16(c[0][nfp * 2],     a[0], bb4[0], bb4[1]);
                mma16(c[1][nfp * 2],     a[1], bb4[0], bb4[1]);
                mma16(c[0][nfp * 2 + 1], a[0], bb4[2], bb4[3]);
                mma16(c[1][nfp * 2 + 1], a[1], bb4[2], bb4[3]);
            }
        }
    }
    __syncthreads();

    float* Cs = (float*)sm;   // staging reuse: 128*132*4 = 67584
    if (sel < 2) {
        #pragma unroll
        for (int mi = 0; mi < 2; mi++) {
            const int m0 = wm * 32 + mi * 16;
            const float bv0 = bias[o0 + m0 + g];
            const float bv1 = bias[o0 + m0 + g + 8];
            #pragma unroll
            for (int nf = 0; nf < 8; nf++) {
                const int nn = wn * 64 + nf * 8 + t4 * 2;
                Cs[(nn)     * 132 + m0 + g]     = c[mi][nf][0] + bv0;
                Cs[(nn + 1) * 132 + m0 + g]     = c[mi][nf][1] + bv0;
                Cs[(nn)     * 132 + m0 + g + 8] = c[mi][nf][2] + bv1;
                Cs[(nn + 1) * 132 + m0 + g + 8] = c[mi][nf][3] + bv1;
            }
        }
        __syncthreads();
        bf16* dstbase = (sel == 0) ? g_q : g_k;
        #pragma unroll
        for (int it = 0; it < 16; it++) {
            const int i = tid + it * 256;
            const int nl = i >> 5, m4 = i & 31;
            const float4 cv = *(const float4*)&Cs[nl * 132 + m4 * 4];
            const int o = o0 + m4 * 4;
            const int h = o >> 6, d = o & 63;
            uint2 pk = make_uint2(pack2(cv.x, cv.y), pack2(cv.z, cv.w));
            *(uint2*)&dstbase[(((size_t)b * NH_ + h) * NTOK_ + n0 + nl) * FH_ + d] = pk;
        }
    } else {
        #pragma unroll
        for (int mi = 0; mi < 2; mi++) {
            #pragma unroll
            for (int half = 0; half < 2; half++) {
                const int m = wm * 32 + mi * 16 + g + half * 8;
                const int o = o0 + m;
                const int h = o >> 6, d = o & 63;
                const float bval = bias[o];
                bf16* dst = g_v + (((size_t)b * NH_ + h) * FH_ + d) * NTOK_ + n0;
                #pragma unroll
                for (int nf = 0; nf < 8; nf++) {
                    const int nn = wn * 64 + nf * 8 + t4 * 2;
                    *(uint32_t*)&dst[nn] = pack2(c[mi][nf][half * 2] + bval,
                                                 c[mi][nf][half * 2 + 1] + bval);
                }
            }
        }
    }
}

// ---------------------------------------------------------------------------
// Kernel 2: attention. Register-resident P, bf16x2 ex2, 3-buffer K/V,
// one barrier per chunk. O-MMA issued BEFORE row-sum reductions so the
// shuffle chain overlaps in-flight HMMAs. Smem 55296B.
#define KVSTG 9216     // bytes per K or V stage
__global__ __launch_bounds__(256, 2) void attn_kernel() {
    extern __shared__ uint32_t sm[];
    const uint32_t sb = smem_u32(sm);
    const uint32_t KsB = sb, VsB = sb + 3 * KVSTG;

    const int tid = threadIdx.x;
    const int warp = tid >> 5, lane = tid & 31;
    const int g = lane >> 2, t4 = lane & 3;
    const int m0 = warp * 16;
    const int qt = blockIdx.x, h = blockIdx.y, b = blockIdx.z;
    const size_t hb = (size_t)(b * NH_ + h);
    const bf16* qsrc = g_q + hb * NTOK_ * FH_ + (size_t)qt * 128 * FH_;
    const bf16* ksrc = g_k + hb * NTOK_ * FH_;
    const bf16* vsrc = g_v + hb * FH_ * NTOK_;

    const uint32_t kvoff = (uint32_t)(((lane >> 4) * 8 + (lane & 7)) * 144
                                      + ((lane >> 3) & 1) * 16);

    uint32_t qf[4][4];
    {
        const uint32_t* q0 = (const uint32_t*)(qsrc + (size_t)(m0 + g) * FH_);
        const uint32_t* q1 = (const uint32_t*)(qsrc + (size_t)(m0 + g + 8) * FH_);
        #pragma unroll
        for (int s = 0; s < 4; s++) {
            qf[s][0] = q0[s * 8 + t4];
            qf[s][1] = q1[s * 8 + t4];
            qf[s][2] = q0[s * 8 + t4 + 4];
            qf[s][3] = q1[s * 8 + t4 + 4];
        }
    }

    auto loadKV = [&](int ck, int st) {
        const int c0 = ck * 64;
        #pragma unroll
        for (int it = 0; it < 2; it++) {
            const int i = tid + it * 256;
            const int r = i >> 3, c8 = i & 7;
            cp16(KsB + (uint32_t)(st * KVSTG + r * 144 + c8 * 16),
                 ksrc + (size_t)(c0 + r) * FH_ + c8 * 8);
            cp16(VsB + (uint32_t)(st * KVSTG + r * 144 + c8 * 16),
                 vsrc + (size_t)r * NTOK_ + c0 + c8 * 8);
        }
    };

    float oacc[8][4];
    #pragma unroll
    for (int nf = 0; nf < 8; nf++)
        #pragma unroll
        for (int q = 0; q < 4; q++) oacc[nf][q] = 0.f;
    float l0 = 0.f, l1 = 0.f;

    loadKV(0, 0); CP_COMMIT();
    loadKV(1, 1); CP_COMMIT();

    const float SC = 0.125f * 1.4426950408889634f;   // 1/sqrt(64) * log2(e)

    for (int ck = 0; ck < 16; ck++) {
        if (ck + 1 < 16) CP_WAIT(1); else CP_WAIT(0);
        __syncthreads();
        if (ck + 2 < 16) { loadKV(ck + 2, (ck + 2) % 3); CP_COMMIT(); }
        const uint32_t Kb = KsB + (uint32_t)((ck % 3) * KVSTG);
        const uint32_t Vb = VsB + (uint32_t)((ck % 3) * KVSTG);

        // S = Q K^T
        float sc[8][4];
        #pragma unroll
        for (int nf = 0; nf < 8; nf++)
            #pragma unroll
            for (int q = 0; q < 4; q++) sc[nf][q] = 0.f;
        #pragma unroll
        for (int s = 0; s < 4; s++) {
            #pragma unroll
            for (int nfp = 0; nfp < 4; nfp++) {
                uint32_t bb4[4];
                ldsm4(bb4, Kb + kvoff + nfp * 16 * 144 + s * 32);
                mma16(sc[nfp * 2],     qf[s], bb4[0], bb4[1]);
                mma16(sc[nfp * 2 + 1], qf[s], bb4[2], bb4[3]);
            }
        }

        // P = exp2(S*SC) in bf16x2 pairs (A-fragment layout), register-resident
        uint32_t pb[8][2];
        #pragma unroll
        for (int nf = 0; nf < 8; nf++) {
            pb[nf][0] = ex2_bf16x2(pack2(sc[nf][0] * SC, sc[nf][1] * SC));
            pb[nf][1] = ex2_bf16x2(pack2(sc[nf][2] * SC, sc[nf][3] * SC));
        }

        // O += P V^T immediately (tensor pipe busy while we reduce sums below)
        #pragma unroll
        for (int s = 0; s < 4; s++) {
            const uint32_t pa[4] = { pb[2 * s][0], pb[2 * s][1],
                                     pb[2 * s + 1][0], pb[2 * s + 1][1] };
            #pragma unroll
            for (int nfp = 0; nfp < 4; nfp++) {
                uint32_t bb4[4];
                ldsm4(bb4, Vb + kvoff + nfp * 16 * 144 + s * 32);
                mma16(oacc[nfp * 2],     pa, bb4[0], bb4[1]);
                mma16(oacc[nfp * 2 + 1], pa, bb4[2], bb4[3]);
            }
        }

        // Row-sum reductions overlap the in-flight O-MMAs
        float s0 = 0.f, s1 = 0.f;
        #pragma unroll
        for (int nf = 0; nf < 8; nf++) {
            const float2 f0 = __bfloat1622float2(*(__nv_bfloat162*)&pb[nf][0]);
            const float2 f1 = __bfloat1622float2(*(__nv_bfloat162*)&pb[nf][1]);
            s0 += f0.x + f0.y;
            s1 += f1.x + f1.y;
        }
        s0 += __shfl_xor_sync(0xffffffffu, s0, 1);
        s0 += __shfl_xor_sync(0xffffffffu, s0, 2);
        s1 += __shfl_xor_sync(0xffffffffu, s1, 1);
        s1 += __shfl_xor_sync(0xffffffffu, s1, 2);
        l0 += s0; l1 += s1;
    }

    const float inv0 = 1.f / l0, inv1 = 1.f / l1;
    bf16* d0 = g_o + ((size_t)b * NTOK_ + qt * 128 + m0 + g) * COUT_ + h * FH_;
    bf16* d1 = d0 + 8 * COUT_;
    #pragma unroll
    for (int nf = 0; nf < 8; nf++) {
        const int dd = nf * 8 + t4 * 2;
        *(uint32_t*)&d0[dd] = pack2(oacc[nf][0] * inv0, oacc[nf][1] * inv0);
        *(uint32_t*)&d1[dd] = pack2(oacc[nf][2] * inv1, oacc[nf][3] * inv1);
    }
}

// ---------------------------------------------------------------------------
// Kernel 3: output projection + bias + residual, 3-stage pipeline.
__global__ __launch_bounds__(256, 2) void oproj_gemm(
    const float* __restrict__ x, const float* __restrict__ bo, float* __restrict__ out)
{
    extern __shared__ uint32_t sm[];
    const uint32_t sb = smem_u32(sm);

    const int tid = threadIdx.x;
    const int warp = tid >> 5, lane = tid & 31;
    const int g = lane >> 2, t4 = lane & 3;
    const int wm = warp & 3, wn = warp >> 2;
    const int nt = blockIdx.x, mt = blockIdx.y, b = blockIdx.z;
    const int o0 = mt * 128, n0 = nt * 128;
    const bf16* asrc = g_wo + (size_t)o0 * COUT_;
    const bf16* bsrc = g_o + ((size_t)b * NTOK_ + n0) * COUT_;

    const uint32_t aoff = (uint32_t)((wm * 32 + (lane & 15)) * 80 + (lane >> 4) * 16);
    const uint32_t boff = (uint32_t)((wn * 64 + (lane >> 4) * 8 + (lane & 7)) * 80
                                     + ((lane >> 3) & 1) * 16);

    auto loadAB = [&](int kc, int st) {
        const uint32_t ab = sb + (uint32_t)(st * 2 * TSZB);
        const uint32_t bb = ab + TSZB;
        #pragma unroll
        for (int it = 0; it < 2; it++) {
            const int i = tid + it * 256;
            const int r = i >> 2, c4 = i & 3;
            cp16(ab + (uint32_t)(r * 80 + c4 * 16), asrc + (size_t)r * COUT_ + kc * 32 + c4 * 8);
            cp16(bb + (uint32_t)(r * 80 + c4 * 16), bsrc + (size_t)r * COUT_ + kc * 32 + c4 * 8);
        }
    };

    float c[2][8][4];
    #pragma unroll
    for (int mi = 0; mi < 2; mi++)
        #pragma unroll
        for (int nf = 0; nf < 8; nf++)
            #pragma unroll
            for (int q = 0; q < 4; q++) c[mi][nf][q] = 0.f;

    loadAB(0, 0); CP_COMMIT();
    loadAB(1, 1); CP_COMMIT();

    const int NK = 16;
    for (int kc = 0; kc < NK; kc++) {
        if (kc + 1 < NK) CP_WAIT(1); else CP_WAIT(0);
        __syncthreads();
        if (kc + 2 < NK) { loadAB(kc + 2, (kc + 2) % 3); CP_COMMIT(); }
        const uint32_t Ab = sb + (uint32_t)((kc % 3) * 2 * TSZB);
        const uint32_t Bb = Ab + TSZB;
        #pragma unroll
        for (int s = 0; s < 2; s++) {
            uint32_t a[2][4];
            ldsm4(a[0], Ab + aoff + s * 32);
            ldsm4(a[1], Ab + aoff + 16 * 80 + s * 32);
            #pragma unroll
            for (int nfp = 0; nfp < 4; nfp++) {
                uint32_t bb4[4];
                ldsm4(bb4, Bb + boff + nfp * 16 * 80 + s * 32);
                mma16(c[0][nfp * 2],     a[0], bb4[0], bb4[1]);
                mma16(c[1][nfp * 2],     a[1], bb4[0], bb4[1]);
                mma16(c[0][nfp * 2 + 1], a[0], bb4[2], bb4[3]);
                mma16(c[1][nfp * 2 + 1], a[1], bb4[2], bb4[3]);
            }
        }
    }

    #pragma unroll
    for (int mi = 0; mi < 2; mi++) {
        #pragma unroll
        for (int half = 0; half < 2; half++) {
            const int m = o0 + wm * 32 + mi * 16 + g + half * 8;
            const float bval = bo[m];
            const float* xr = x + ((size_t)b * FIN_ + m) * NTOK_ + n0;
            float* outr = out + ((size_t)b * FIN_ + m) * NTOK_ + n0;
            #pragma unroll
            for (int nf = 0; nf < 8; nf++) {
                const int nn = wn * 64 + nf * 8 + t4 * 2;
                const float2 xv = *(const float2*)&xr[nn];
                *(float2*)&outr[nn] = make_float2(xv.x + bval + c[mi][nf][half * 2],
                                                  xv.y + bval + c[mi][nf][half * 2 + 1]);
            }
        }
    }
}

// ---------------------------------------------------------------------------
extern "C" void kernel_launch(void* const* d_in, const int* in_sizes, int n_in,
                              void* d_out, int out_size)
{
    const float* x  = (const float*)d_in[0];
    const float* wq = (const float*)d_in[1];
    const float* bq = (const float*)d_in[2];
    const float* wk = (const float*)d_in[3];
    const float* bk = (const float*)d_in[4];
    const float* wv = (const float*)d_in[5];
    const float* bv = (const float*)d_in[6];
    const float* wo = (const float*)d_in[7];
    const float* bo = (const float*)d_in[8];
    float* out = (float*)d_out;

    const int qkv_smem   = 128 * 132 * 4;        // 67584 (pipeline 61440, staging 67584)
    const int oproj_smem = 3 * 2 * TSZB;         // 61440
    const int attn_smem  = 6 * KVSTG;            // 55296
    cudaFuncSetAttribute(qkv_gemm,    cudaFuncAttributeMaxDynamicSharedMemorySize, qkv_smem);
    cudaFuncSetAttribute(oproj_gemm,  cudaFuncAttributeMaxDynamicSharedMemorySize, oproj_smem);
    cudaFuncSetAttribute(attn_kernel, cudaFuncAttributeMaxDynamicSharedMemorySize, attn_smem);

    prep_pack<<<512 + 1728 + 512, 256>>>(x, wq, wk, wv, wo);
    qkv_gemm<<<dim3(8, 12, 16), 256, qkv_smem>>>(bq, bk, bv);
    attn_kernel<<<dim3(8, NH_, B_), 256, attn_smem>>>();
    oproj_gemm<<<dim3(8, 2, 16), 256, oproj_smem>>>(x, bo, out);
}